// round 9
// baseline (speedup 1.0000x reference)
#include <cuda_runtime.h>
#include <math.h>
#include <stdlib.h>

#define N_NODES 10000
#define C_IN    128
#define D_OUT   20
#define KNN     16
#define NCHUNK  4
#define NE      (N_NODES*KNN)      // 160000 edges

// Default-priority constructor (allowed), no CUDA calls: eager module loading.
__attribute__((constructor)) static void force_eager_loading(void) {
    setenv("CUDA_MODULE_LOADING", "EAGER", 1);
}

// ---------------- device scratch (device-side access ONLY; never passed from host) ----------------
__device__ float  g_h   [N_NODES*D_OUT];
__device__ float  g_emb [N_NODES*D_OUT];
__device__ float  g_embn[N_NODES*D_OUT];
__device__ float  g_sqe [N_NODES];
__device__ float  g_sqp [N_NODES];
__device__ double g_sqed[N_NODES];         // exact double row norms (emb)
__device__ float  g_mu  [D_OUT];
__device__ float  g_rstd[D_OUT];
__device__ int    g_pi_e[NCHUNK*N_NODES*KNN];
__device__ int    g_pi_p[NCHUNK*N_NODES*KNN];
__device__ float  g_pd_p[NCHUNK*N_NODES*KNN];   // pos keeps its f32 distances
__device__ int    g_idx_e[NE];
__device__ int    g_idx_p[NE];

// ---------------- 1. GEMM h = x@W + b ----------------
__global__ __launch_bounds__(128, 1) void gemm_kernel(const float* __restrict__ x,
                                                      const float* __restrict__ W,
                                                      const float* __restrict__ b) {
    __shared__ float Ws[C_IN*D_OUT];          // 128x20
    __shared__ float xs[128][17];             // 16 cols + pad

    int tid = threadIdx.x;
    for (int i = tid; i < C_IN*D_OUT; i += 128) Ws[i] = W[i];

    int row0 = blockIdx.x * 128;
    int row  = row0 + tid;

    float acc[D_OUT];
#pragma unroll
    for (int d = 0; d < D_OUT; d++) acc[d] = 0.f;

    for (int ct = 0; ct < C_IN/16; ct++) {
        __syncthreads();
        for (int idx = tid; idx < 128*16; idx += 128) {
            int r = idx >> 4, c = idx & 15;
            int gr = row0 + r;
            xs[r][c] = (gr < N_NODES) ? x[gr*C_IN + ct*16 + c] : 0.f;
        }
        __syncthreads();
#pragma unroll
        for (int c = 0; c < 16; c++) {
            float xv = xs[tid][c];
            const float* wrow = &Ws[(ct*16+c)*D_OUT];
#pragma unroll
            for (int d = 0; d < D_OUT; d++) acc[d] = __fmaf_rn(xv, wrow[d], acc[d]);
        }
    }

    if (row < N_NODES) {
#pragma unroll
        for (int d = 0; d < D_OUT; d++) g_h[row*D_OUT + d] = __fadd_rn(acc[d], b[d]);
    }
}

// ---------------- 2. deterministic BN stats: one block per channel ----------------
__global__ __launch_bounds__(256, 1) void bn_stats() {
    int d   = blockIdx.x;            // 0..D_OUT-1
    int tid = threadIdx.x;
    __shared__ double ss[256];
    __shared__ double sq[256];
    double s = 0.0, s2 = 0.0;
    for (int i = tid; i < N_NODES; i += 256) {
        double v = (double)g_h[i*D_OUT + d];
        s  += v;
        s2 += v*v;
    }
    ss[tid] = s; sq[tid] = s2;
    __syncthreads();
    for (int o = 128; o > 0; o >>= 1) {
        if (tid < o) { ss[tid] += ss[tid+o]; sq[tid] += sq[tid+o]; }
        __syncthreads();
    }
    if (tid == 0) {
        double mu  = ss[0] / (double)N_NODES;
        double var = sq[0] / (double)N_NODES - mu*mu;
        g_mu[d]   = (float)mu;
        g_rstd[d] = (float)(1.0 / sqrt(var + 1e-5));
    }
}

// ---------------- 3. emb = relu(bn(h)); embn; norms (f32; + exact double for emb) ----------------
__global__ __launch_bounds__(128, 1) void emb_kernel(const float* __restrict__ noise,
                                                     const float* __restrict__ pos,
                                                     const float* __restrict__ gamma,
                                                     const float* __restrict__ beta) {
    int i = blockIdx.x*128 + threadIdx.x;
    if (i >= N_NODES) return;
    float  se  = 0.f;
    double sed = 0.0;
#pragma unroll
    for (int d = 0; d < D_OUT; d++) {
        float h = g_h[i*D_OUT + d];
        float v = __fadd_rn(__fmul_rn(__fmul_rn(__fsub_rn(h, g_mu[d]), g_rstd[d]), gamma[d]), beta[d]);
        float e = fmaxf(v, 0.f);
        g_emb [i*D_OUT + d] = e;
        g_embn[i*D_OUT + d] = __fadd_rn(e, __fmul_rn(noise[i*D_OUT + d], 1e-4f));
        se  = __fadd_rn(se, __fmul_rn(e, e));
        sed = fma((double)e, (double)e, sed);
    }
    g_sqe [i] = se;
    g_sqed[i] = sed;
    float sp = 0.f;
#pragma unroll
    for (int c = 0; c < 3; c++) {
        float v = pos[i*3 + c];
        sp = __fadd_rn(sp, __fmul_rn(v, v));
    }
    g_sqp[i] = sp;
}

// ---------------- 4. KNN prefilter: f32, thread-per-query, 4-way j-split ----------------
// WHICH==0 (emb): stores candidate indices only (double rescore later).
// WHICH==1 (pos): stores f32 distances too (they ARE the final ordering values).
template<int DIM, int WHICH>
__global__ __launch_bounds__(128, 1) void knn_kernel(const float* __restrict__ pos_ext) {
    constexpr int TJ = 64;
    __shared__ float shf[TJ*DIM];
    __shared__ float shsq[TJ];
    __shared__ float s_kd[KNN*128];
    __shared__ int   s_ki[KNN*128];

    const float* feat = WHICH ? pos_ext : (const float*)g_emb;
    const float* sq   = WHICH ? (const float*)g_sqp : (const float*)g_sqe;
    int*   pi         = WHICH ? g_pi_p : g_pi_e;

    int tid = threadIdx.x;
    int q   = blockIdx.x*128 + tid;
    bool valid = q < N_NODES;
    int qq = valid ? q : 0;

    float qf[DIM];
#pragma unroll
    for (int c = 0; c < DIM; c++) qf[c] = feat[qq*DIM + c];
    float sqq = sq[qq];

#pragma unroll
    for (int k = 0; k < KNN; k++) { s_kd[k*128+tid] = INFINITY; s_ki[k*128+tid] = 0x7fffffff; }
    float worst = INFINITY;

    const int clen = N_NODES / NCHUNK;        // 2500
    int j0 = blockIdx.y * clen;
    int j1 = j0 + clen;

    for (int jt = j0; jt < j1; jt += TJ) {
        __syncthreads();
        int cnt = min(TJ, j1 - jt);
        for (int idx = tid; idx < cnt*DIM; idx += 128) shf[idx]  = feat[jt*DIM + idx];
        for (int idx = tid; idx < cnt;     idx += 128) shsq[idx] = sq[jt + idx];
        __syncthreads();
        for (int t = 0; t < cnt; t++) {
            int j = jt + t;
            float dot = 0.f;
            if (DIM == 20) {
                const float4* rowv = (const float4*)&shf[t*DIM];
#pragma unroll
                for (int v = 0; v < 5; v++) {
                    float4 f = rowv[v];
                    dot = __fmaf_rn(qf[4*v+0], f.x, dot);
                    dot = __fmaf_rn(qf[4*v+1], f.y, dot);
                    dot = __fmaf_rn(qf[4*v+2], f.z, dot);
                    dot = __fmaf_rn(qf[4*v+3], f.w, dot);
                }
            } else {
#pragma unroll
                for (int c = 0; c < DIM; c++) dot = __fmaf_rn(qf[c], shf[t*DIM + c], dot);
            }
            // exact reference formula: (sq_i + sq_j) - 2*dot, separate roundings
            float d2 = __fsub_rn(__fadd_rn(sqq, shsq[t]), __fmul_rn(2.0f, dot));
            if (j == q) continue;
            if (d2 < worst) {                      // strict <: earlier (lower) j wins ties
                s_kd[(KNN-1)*128+tid] = d2; s_ki[(KNN-1)*128+tid] = j;
#pragma unroll
                for (int s = KNN-1; s > 0; --s) {
                    float a = s_kd[s*128+tid], bb = s_kd[(s-1)*128+tid];
                    if (a < bb) {
                        s_kd[s*128+tid] = bb; s_kd[(s-1)*128+tid] = a;
                        int ti = s_ki[s*128+tid];
                        s_ki[s*128+tid] = s_ki[(s-1)*128+tid];
                        s_ki[(s-1)*128+tid] = ti;
                    }
                }
                worst = s_kd[(KNN-1)*128+tid];
            }
        }
    }

    if (valid) {
        int base = (blockIdx.y*N_NODES + q)*KNN;
#pragma unroll
        for (int k = 0; k < KNN; k++) pi[base+k] = s_ki[k*128+tid];
        if (WHICH) {
#pragma unroll
            for (int k = 0; k < KNN; k++) g_pd_p[base+k] = s_kd[k*128+tid];
        }
    }
}

// ---------------- 5a. emb merge: DOUBLE-precision rescore of the 64 candidates ----------------
// Correctly-rounded d2 (best estimator of the reference's f32 value for D=20),
// cast to f32, lowest-index tie-break => matches top_k semantics.
__global__ __launch_bounds__(128, 1) void merge_emb_kernel() {
    __shared__ float s_kd[KNN*128];
    __shared__ int   s_ki[KNN*128];
    int tid = threadIdx.x;
    int q = blockIdx.x*128 + tid;
    bool valid = q < N_NODES;
    int qq = valid ? q : 0;

    float qf[D_OUT];
#pragma unroll
    for (int c = 0; c < D_OUT; c++) qf[c] = g_emb[qq*D_OUT + c];
    double sqq = g_sqed[qq];

#pragma unroll
    for (int k = 0; k < KNN; k++) { s_kd[k*128+tid] = INFINITY; s_ki[k*128+tid] = 0x7fffffff; }
    float worst  = INFINITY;
    int   worsti = 0x7fffffff;

    for (int c = 0; c < NCHUNK; c++) {
        int base = (c*N_NODES + qq)*KNN;
        for (int k = 0; k < KNN; k++) {
            int j = g_pi_e[base + k];
            const float* row = &g_emb[j*D_OUT];
            double dot = 0.0;
#pragma unroll
            for (int d = 0; d < D_OUT; d++) dot = fma((double)qf[d], (double)row[d], dot);
            double d2d = (sqq + g_sqed[j]) - 2.0*dot;
            float  df  = (float)d2d;
            if (df < worst || (df == worst && j < worsti)) {
                s_kd[(KNN-1)*128+tid] = df; s_ki[(KNN-1)*128+tid] = j;
#pragma unroll
                for (int s = KNN-1; s > 0; --s) {
                    float a = s_kd[s*128+tid], bb = s_kd[(s-1)*128+tid];
                    int  ai = s_ki[s*128+tid], bi = s_ki[(s-1)*128+tid];
                    if (a < bb || (a == bb && ai < bi)) {
                        s_kd[s*128+tid] = bb; s_kd[(s-1)*128+tid] = a;
                        s_ki[s*128+tid] = bi; s_ki[(s-1)*128+tid] = ai;
                    }
                }
                worst  = s_kd[(KNN-1)*128+tid];
                worsti = s_ki[(KNN-1)*128+tid];
            }
        }
    }
    if (valid) {
#pragma unroll
        for (int k = 0; k < KNN; k++) g_idx_e[q*KNN + k] = s_ki[k*128+tid];
    }
}

// ---------------- 5b. pos merge: stable merge of STORED f32 distances ----------------
// Pos ordering must reproduce the reference's f32-computed d2 ordering, which the
// prefilter's identical f32 formula already produces. Chunk-ascending arrival +
// strict-< insertion => lowest-index-first on exact f32 ties (top_k semantics).
__global__ __launch_bounds__(128, 1) void merge_pos_kernel() {
    __shared__ float s_kd[KNN*128];
    __shared__ int   s_ki[KNN*128];
    int tid = threadIdx.x;
    int q = blockIdx.x*128 + tid;
    bool valid = q < N_NODES;
    int qq = valid ? q : 0;

#pragma unroll
    for (int k = 0; k < KNN; k++) { s_kd[k*128+tid] = INFINITY; s_ki[k*128+tid] = 0; }
    float worst = INFINITY;

#pragma unroll
    for (int c = 0; c < NCHUNK; c++) {
        int base = (c*N_NODES + qq)*KNN;
#pragma unroll
        for (int k = 0; k < KNN; k++) {
            float d = g_pd_p[base + k];
            int   i = g_pi_p[base + k];
            if (d < worst) {                      // strict <: first-arrived (lower index) wins ties
                s_kd[(KNN-1)*128+tid] = d; s_ki[(KNN-1)*128+tid] = i;
#pragma unroll
                for (int s = KNN-1; s > 0; --s) {
                    float a = s_kd[s*128+tid], bb = s_kd[(s-1)*128+tid];
                    if (a < bb) {
                        s_kd[s*128+tid] = bb; s_kd[(s-1)*128+tid] = a;
                        int ti = s_ki[s*128+tid];
                        s_ki[s*128+tid] = s_ki[(s-1)*128+tid];
                        s_ki[(s-1)*128+tid] = ti;
                    }
                }
                worst = s_kd[(KNN-1)*128+tid];
            }
        }
    }
    if (valid) {
#pragma unroll
        for (int k = 0; k < KNN; k++) g_idx_p[q*KNN + k] = s_ki[k*128+tid];
    }
}

// ---------------- 6. p = exp(-t*dist) and all output sections ----------------
__global__ __launch_bounds__(256, 1) void out_kernel(const float* __restrict__ t,
                                                     float* __restrict__ out,
                                                     int out_size) {
    int e = blockIdx.x*256 + threadIdx.x;
    if (e >= NE) return;
    int i    = e >> 4;
    int srcE = g_idx_e[e];
    int srcP = g_idx_p[e];

    const float* a  = &g_embn[srcE*D_OUT];
    const float* bb = &g_embn[i*D_OUT];
    float ss = 0.f;
#pragma unroll
    for (int c = 0; c < D_OUT; c++) {
        float d = __fsub_rn(a[c], bb[c]);
        ss = __fadd_rn(ss, __fmul_rn(d, d));
    }
    float dist = sqrtf(ss);
    float p = expf(-__fmul_rn(t[0], dist));

    float fi = (float)i, fse = (float)srcE, fsp = (float)srcP;
    // layout: p | soft_index_v[2] | edges_large[2] | edge_index[2,2E]
    int off;
    off = 0*NE + e; if (off < out_size) out[off] = p;    // p
    off = 1*NE + e; if (off < out_size) out[off] = p;    // soft_index_v row0
    off = 2*NE + e; if (off < out_size) out[off] = fi;   // soft_index_v row1 (dst)
    off = 3*NE + e; if (off < out_size) out[off] = fse;  // edges_large row0 (src)
    off = 4*NE + e; if (off < out_size) out[off] = fi;   // edges_large row1 (dst)
    off = 5*NE + e; if (off < out_size) out[off] = fse;  // edge_index row0: src_large
    off = 6*NE + e; if (off < out_size) out[off] = fsp;  // edge_index row0: src_pos
    off = 7*NE + e; if (off < out_size) out[off] = fi;   // edge_index row1: dst_large
    off = 8*NE + e; if (off < out_size) out[off] = fi;   // edge_index row1: dst_pos
}

// ---------------- launcher (passes ONLY harness-provided pointers) ----------------
extern "C" void kernel_launch(void* const* d_in, const int* in_sizes, int n_in,
                              void* d_out, int out_size) {
    const float* x     = (const float*)d_in[0];
    const float* pos   = (const float*)d_in[1];
    const float* noise = (const float*)d_in[2];
    const float* W     = (const float*)d_in[3];
    const float* b     = (const float*)d_in[4];
    const float* gamma = (const float*)d_in[5];
    const float* beta  = (const float*)d_in[6];
    const float* t     = (const float*)d_in[7];
    float* out = (float*)d_out;

    int nb = (N_NODES + 127) / 128;   // 79

    gemm_kernel<<<nb, 128>>>(x, W, b);
    bn_stats<<<D_OUT, 256>>>();
    emb_kernel<<<nb, 128>>>(noise, pos, gamma, beta);

    {
        dim3 g(nb, NCHUNK);
        knn_kernel<D_OUT, 0><<<g, 128>>>(nullptr);
        knn_kernel<3,     1><<<g, 128>>>(pos);
    }
    merge_emb_kernel<<<nb, 128>>>();
    merge_pos_kernel<<<nb, 128>>>();

    out_kernel<<<(NE + 255)/256, 256>>>(t, out, out_size);
}

// round 11
// speedup vs baseline: 1.0733x; 1.0733x over previous
#include <cuda_runtime.h>
#include <math.h>
#include <stdlib.h>

#define N_NODES 10000
#define C_IN    128
#define D_OUT   20
#define KNN     16
#define NCHUNK  8
#define NE      (N_NODES*KNN)      // 160000 edges

// Default-priority constructor (allowed), no CUDA calls: eager module loading.
__attribute__((constructor)) static void force_eager_loading(void) {
    setenv("CUDA_MODULE_LOADING", "EAGER", 1);
}

// ---------------- device scratch (device-side access ONLY; never passed from host) ----------------
__device__ float  g_h   [N_NODES*D_OUT];
__device__ float  g_emb [N_NODES*D_OUT];
__device__ float  g_embn[N_NODES*D_OUT];
__device__ float  g_sqe [N_NODES];
__device__ float  g_sqp [N_NODES];
__device__ double g_sqed[N_NODES];         // exact double row norms (emb)
__device__ float  g_mu  [D_OUT];
__device__ float  g_rstd[D_OUT];
__device__ int    g_pi_e[NCHUNK*N_NODES*KNN];
__device__ int    g_pi_p[NCHUNK*N_NODES*KNN];
__device__ float  g_pd_p[NCHUNK*N_NODES*KNN];   // pos keeps its f32 distances
__device__ int    g_idx_e[NE];
__device__ int    g_idx_p[NE];

// ---------------- 1. GEMM h = x@W + b ----------------
__global__ __launch_bounds__(128, 1) void gemm_kernel(const float* __restrict__ x,
                                                      const float* __restrict__ W,
                                                      const float* __restrict__ b) {
    __shared__ float Ws[C_IN*D_OUT];          // 128x20
    __shared__ float xs[128][17];             // 16 cols + pad

    int tid = threadIdx.x;
    for (int i = tid; i < C_IN*D_OUT; i += 128) Ws[i] = W[i];

    int row0 = blockIdx.x * 128;
    int row  = row0 + tid;

    float acc[D_OUT];
#pragma unroll
    for (int d = 0; d < D_OUT; d++) acc[d] = 0.f;

    for (int ct = 0; ct < C_IN/16; ct++) {
        __syncthreads();
        for (int idx = tid; idx < 128*16; idx += 128) {
            int r = idx >> 4, c = idx & 15;
            int gr = row0 + r;
            xs[r][c] = (gr < N_NODES) ? x[gr*C_IN + ct*16 + c] : 0.f;
        }
        __syncthreads();
#pragma unroll
        for (int c = 0; c < 16; c++) {
            float xv = xs[tid][c];
            const float* wrow = &Ws[(ct*16+c)*D_OUT];
#pragma unroll
            for (int d = 0; d < D_OUT; d++) acc[d] = __fmaf_rn(xv, wrow[d], acc[d]);
        }
    }

    if (row < N_NODES) {
#pragma unroll
        for (int d = 0; d < D_OUT; d++) g_h[row*D_OUT + d] = __fadd_rn(acc[d], b[d]);
    }
}

// ---------------- 2. deterministic BN stats: one block per channel ----------------
__global__ __launch_bounds__(256, 1) void bn_stats() {
    int d   = blockIdx.x;            // 0..D_OUT-1
    int tid = threadIdx.x;
    __shared__ double ss[256];
    __shared__ double sq[256];
    double s = 0.0, s2 = 0.0;
    for (int i = tid; i < N_NODES; i += 256) {
        double v = (double)g_h[i*D_OUT + d];
        s  += v;
        s2 += v*v;
    }
    ss[tid] = s; sq[tid] = s2;
    __syncthreads();
    for (int o = 128; o > 0; o >>= 1) {
        if (tid < o) { ss[tid] += ss[tid+o]; sq[tid] += sq[tid+o]; }
        __syncthreads();
    }
    if (tid == 0) {
        double mu  = ss[0] / (double)N_NODES;
        double var = sq[0] / (double)N_NODES - mu*mu;
        g_mu[d]   = (float)mu;
        g_rstd[d] = (float)(1.0 / sqrt(var + 1e-5));
    }
}

// ---------------- 3. emb = relu(bn(h)); embn; norms (f32; + exact double for emb) ----------------
__global__ __launch_bounds__(128, 1) void emb_kernel(const float* __restrict__ noise,
                                                     const float* __restrict__ pos,
                                                     const float* __restrict__ gamma,
                                                     const float* __restrict__ beta) {
    int i = blockIdx.x*128 + threadIdx.x;
    if (i >= N_NODES) return;
    float  se  = 0.f;
    double sed = 0.0;
#pragma unroll
    for (int d = 0; d < D_OUT; d++) {
        float h = g_h[i*D_OUT + d];
        float v = __fadd_rn(__fmul_rn(__fmul_rn(__fsub_rn(h, g_mu[d]), g_rstd[d]), gamma[d]), beta[d]);
        float e = fmaxf(v, 0.f);
        g_emb [i*D_OUT + d] = e;
        g_embn[i*D_OUT + d] = __fadd_rn(e, __fmul_rn(noise[i*D_OUT + d], 1e-4f));
        se  = __fadd_rn(se, __fmul_rn(e, e));
        sed = fma((double)e, (double)e, sed);
    }
    g_sqe [i] = se;
    g_sqed[i] = sed;
    float sp = 0.f;
#pragma unroll
    for (int c = 0; c < 3; c++) {
        float v = pos[i*3 + c];
        sp = __fadd_rn(sp, __fmul_rn(v, v));
    }
    g_sqp[i] = sp;
}

// ---------------- 4. KNN prefilter: f32, ILP=4 over j, 8-way chunk split ----------------
// Each j's d2 arithmetic is IDENTICAL to the passing version (same formula, same
// per-j sequential FMA order); only inter-j scheduling (ILP) changed.
// WHICH==0 (emb): stores candidate indices only (double rescore later).
// WHICH==1 (pos): stores f32 distances too (they ARE the final ordering values).
template<int DIM, int WHICH>
__global__ __launch_bounds__(128, 1) void knn_kernel(const float* __restrict__ pos_ext) {
    constexpr int TJ = 64;
    __shared__ float shf[TJ*DIM];
    __shared__ float shsq[TJ];
    __shared__ float s_kd[KNN*128];
    __shared__ int   s_ki[KNN*128];

    const float* feat = WHICH ? pos_ext : (const float*)g_emb;
    const float* sq   = WHICH ? (const float*)g_sqp : (const float*)g_sqe;
    int*   pi         = WHICH ? g_pi_p : g_pi_e;

    int tid = threadIdx.x;
    int q   = blockIdx.x*128 + tid;
    bool valid = q < N_NODES;
    int qq = valid ? q : 0;

    float qf[DIM];
#pragma unroll
    for (int c = 0; c < DIM; c++) qf[c] = feat[qq*DIM + c];
    float sqq = sq[qq];

#pragma unroll
    for (int k = 0; k < KNN; k++) { s_kd[k*128+tid] = INFINITY; s_ki[k*128+tid] = 0x7fffffff; }
    float worst = INFINITY;

    const int clen = N_NODES / NCHUNK;        // 1250
    int j0 = blockIdx.y * clen;
    int j1 = j0 + clen;

#define INSERT_CAND(D2, J)                                                     \
    if ((J) != q && (D2) < worst) {                                            \
        s_kd[(KNN-1)*128+tid] = (D2); s_ki[(KNN-1)*128+tid] = (J);             \
        _Pragma("unroll")                                                      \
        for (int s = KNN-1; s > 0; --s) {                                      \
            float a_ = s_kd[s*128+tid], b_ = s_kd[(s-1)*128+tid];              \
            if (a_ < b_) {                                                     \
                s_kd[s*128+tid] = b_; s_kd[(s-1)*128+tid] = a_;                \
                int t_ = s_ki[s*128+tid];                                      \
                s_ki[s*128+tid] = s_ki[(s-1)*128+tid];                         \
                s_ki[(s-1)*128+tid] = t_;                                      \
            }                                                                  \
        }                                                                      \
        worst = s_kd[(KNN-1)*128+tid];                                         \
    }

    for (int jt = j0; jt < j1; jt += TJ) {
        __syncthreads();
        // padded cooperative load: beyond j1 -> shsq=inf (never inserted), shf=0 (finite)
        for (int idx = tid; idx < TJ*DIM; idx += 128) {
            int jj = jt + idx / DIM;
            shf[idx] = (jj < j1) ? feat[jt*DIM + idx] : 0.f;
        }
        for (int idx = tid; idx < TJ; idx += 128) {
            int jj = jt + idx;
            shsq[idx] = (jj < j1) ? sq[jj] : INFINITY;
        }
        __syncthreads();

        for (int t = 0; t < TJ; t += 4) {
            float dot0 = 0.f, dot1 = 0.f, dot2 = 0.f, dot3 = 0.f;
            if (DIM == 20) {
                const float4* r0 = (const float4*)&shf[(t+0)*DIM];
                const float4* r1 = (const float4*)&shf[(t+1)*DIM];
                const float4* r2 = (const float4*)&shf[(t+2)*DIM];
                const float4* r3 = (const float4*)&shf[(t+3)*DIM];
#pragma unroll
                for (int v = 0; v < 5; v++) {
                    float4 f0 = r0[v], f1 = r1[v], f2 = r2[v], f3 = r3[v];
                    dot0 = __fmaf_rn(qf[4*v+0], f0.x, dot0);
                    dot1 = __fmaf_rn(qf[4*v+0], f1.x, dot1);
                    dot2 = __fmaf_rn(qf[4*v+0], f2.x, dot2);
                    dot3 = __fmaf_rn(qf[4*v+0], f3.x, dot3);
                    dot0 = __fmaf_rn(qf[4*v+1], f0.y, dot0);
                    dot1 = __fmaf_rn(qf[4*v+1], f1.y, dot1);
                    dot2 = __fmaf_rn(qf[4*v+1], f2.y, dot2);
                    dot3 = __fmaf_rn(qf[4*v+1], f3.y, dot3);
                    dot0 = __fmaf_rn(qf[4*v+2], f0.z, dot0);
                    dot1 = __fmaf_rn(qf[4*v+2], f1.z, dot1);
                    dot2 = __fmaf_rn(qf[4*v+2], f2.z, dot2);
                    dot3 = __fmaf_rn(qf[4*v+2], f3.z, dot3);
                    dot0 = __fmaf_rn(qf[4*v+3], f0.w, dot0);
                    dot1 = __fmaf_rn(qf[4*v+3], f1.w, dot1);
                    dot2 = __fmaf_rn(qf[4*v+3], f2.w, dot2);
                    dot3 = __fmaf_rn(qf[4*v+3], f3.w, dot3);
                }
            } else {
#pragma unroll
                for (int c = 0; c < DIM; c++) {
                    dot0 = __fmaf_rn(qf[c], shf[(t+0)*DIM + c], dot0);
                    dot1 = __fmaf_rn(qf[c], shf[(t+1)*DIM + c], dot1);
                    dot2 = __fmaf_rn(qf[c], shf[(t+2)*DIM + c], dot2);
                    dot3 = __fmaf_rn(qf[c], shf[(t+3)*DIM + c], dot3);
                }
            }
            // exact reference formula per j: (sq_i + sq_j) - 2*dot, separate roundings
            float d2_0 = __fsub_rn(__fadd_rn(sqq, shsq[t+0]), __fmul_rn(2.0f, dot0));
            float d2_1 = __fsub_rn(__fadd_rn(sqq, shsq[t+1]), __fmul_rn(2.0f, dot1));
            float d2_2 = __fsub_rn(__fadd_rn(sqq, shsq[t+2]), __fmul_rn(2.0f, dot2));
            float d2_3 = __fsub_rn(__fadd_rn(sqq, shsq[t+3]), __fmul_rn(2.0f, dot3));
            int jb = jt + t;
            // inserts in ascending-j order => stability preserved
            INSERT_CAND(d2_0, jb+0);
            INSERT_CAND(d2_1, jb+1);
            INSERT_CAND(d2_2, jb+2);
            INSERT_CAND(d2_3, jb+3);
        }
    }
#undef INSERT_CAND

    if (valid) {
        int base = (blockIdx.y*N_NODES + q)*KNN;
#pragma unroll
        for (int k = 0; k < KNN; k++) pi[base+k] = s_ki[k*128+tid];
        if (WHICH) {
#pragma unroll
            for (int k = 0; k < KNN; k++) g_pd_p[base+k] = s_kd[k*128+tid];
        }
    }
}

// ---------------- 5a. emb merge: DOUBLE-precision rescore of the 128 candidates ----------------
// Correctly-rounded d2 (best estimator of the reference's f32 value for D=20),
// cast to f32, lowest-index tie-break => matches top_k semantics.
__global__ __launch_bounds__(128, 1) void merge_emb_kernel() {
    __shared__ float s_kd[KNN*128];
    __shared__ int   s_ki[KNN*128];
    int tid = threadIdx.x;
    int q = blockIdx.x*128 + tid;
    bool valid = q < N_NODES;
    int qq = valid ? q : 0;

    float qf[D_OUT];
#pragma unroll
    for (int c = 0; c < D_OUT; c++) qf[c] = g_emb[qq*D_OUT + c];
    double sqq = g_sqed[qq];

#pragma unroll
    for (int k = 0; k < KNN; k++) { s_kd[k*128+tid] = INFINITY; s_ki[k*128+tid] = 0x7fffffff; }
    float worst  = INFINITY;
    int   worsti = 0x7fffffff;

    for (int c = 0; c < NCHUNK; c++) {
        int base = (c*N_NODES + qq)*KNN;
        for (int k = 0; k < KNN; k++) {
            int j = g_pi_e[base + k];
            const float* row = &g_emb[j*D_OUT];
            double dot = 0.0;
#pragma unroll
            for (int d = 0; d < D_OUT; d++) dot = fma((double)qf[d], (double)row[d], dot);
            double d2d = (sqq + g_sqed[j]) - 2.0*dot;
            float  df  = (float)d2d;
            if (df < worst || (df == worst && j < worsti)) {
                s_kd[(KNN-1)*128+tid] = df; s_ki[(KNN-1)*128+tid] = j;
#pragma unroll
                for (int s = KNN-1; s > 0; --s) {
                    float a = s_kd[s*128+tid], bb = s_kd[(s-1)*128+tid];
                    int  ai = s_ki[s*128+tid], bi = s_ki[(s-1)*128+tid];
                    if (a < bb || (a == bb && ai < bi)) {
                        s_kd[s*128+tid] = bb; s_kd[(s-1)*128+tid] = a;
                        s_ki[s*128+tid] = bi; s_ki[(s-1)*128+tid] = ai;
                    }
                }
                worst  = s_kd[(KNN-1)*128+tid];
                worsti = s_ki[(KNN-1)*128+tid];
            }
        }
    }
    if (valid) {
#pragma unroll
        for (int k = 0; k < KNN; k++) g_idx_e[q*KNN + k] = s_ki[k*128+tid];
    }
}

// ---------------- 5b. pos merge: stable merge of STORED f32 distances ----------------
// Chunk-ascending arrival + strict-< insertion => lowest-index-first on exact
// f32 ties (top_k semantics). Values identical to the prefilter's f32 d2.
__global__ __launch_bounds__(128, 1) void merge_pos_kernel() {
    __shared__ float s_kd[KNN*128];
    __shared__ int   s_ki[KNN*128];
    int tid = threadIdx.x;
    int q = blockIdx.x*128 + tid;
    bool valid = q < N_NODES;
    int qq = valid ? q : 0;

#pragma unroll
    for (int k = 0; k < KNN; k++) { s_kd[k*128+tid] = INFINITY; s_ki[k*128+tid] = 0; }
    float worst = INFINITY;

#pragma unroll
    for (int c = 0; c < NCHUNK; c++) {
        int base = (c*N_NODES + qq)*KNN;
#pragma unroll
        for (int k = 0; k < KNN; k++) {
            float d = g_pd_p[base + k];
            int   i = g_pi_p[base + k];
            if (d < worst) {
                s_kd[(KNN-1)*128+tid] = d; s_ki[(KNN-1)*128+tid] = i;
#pragma unroll
                for (int s = KNN-1; s > 0; --s) {
                    float a = s_kd[s*128+tid], bb = s_kd[(s-1)*128+tid];
                    if (a < bb) {
                        s_kd[s*128+tid] = bb; s_kd[(s-1)*128+tid] = a;
                        int ti = s_ki[s*128+tid];
                        s_ki[s*128+tid] = s_ki[(s-1)*128+tid];
                        s_ki[(s-1)*128+tid] = ti;
                    }
                }
                worst = s_kd[(KNN-1)*128+tid];
            }
        }
    }
    if (valid) {
#pragma unroll
        for (int k = 0; k < KNN; k++) g_idx_p[q*KNN + k] = s_ki[k*128+tid];
    }
}

// ---------------- 6. p = exp(-t*dist) and all output sections ----------------
__global__ __launch_bounds__(256, 1) void out_kernel(const float* __restrict__ t,
                                                     float* __restrict__ out,
                                                     int out_size) {
    int e = blockIdx.x*256 + threadIdx.x;
    if (e >= NE) return;
    int i    = e >> 4;
    int srcE = g_idx_e[e];
    int srcP = g_idx_p[e];

    const float* a  = &g_embn[srcE*D_OUT];
    const float* bb = &g_embn[i*D_OUT];
    float ss = 0.f;
#pragma unroll
    for (int c = 0; c < D_OUT; c++) {
        float d = __fsub_rn(a[c], bb[c]);
        ss = __fadd_rn(ss, __fmul_rn(d, d));
    }
    float dist = sqrtf(ss);
    float p = expf(-__fmul_rn(t[0], dist));

    float fi = (float)i, fse = (float)srcE, fsp = (float)srcP;
    // layout: p | soft_index_v[2] | edges_large[2] | edge_index[2,2E]
    int off;
    off = 0*NE + e; if (off < out_size) out[off] = p;    // p
    off = 1*NE + e; if (off < out_size) out[off] = p;    // soft_index_v row0
    off = 2*NE + e; if (off < out_size) out[off] = fi;   // soft_index_v row1 (dst)
    off = 3*NE + e; if (off < out_size) out[off] = fse;  // edges_large row0 (src)
    off = 4*NE + e; if (off < out_size) out[off] = fi;   // edges_large row1 (dst)
    off = 5*NE + e; if (off < out_size) out[off] = fse;  // edge_index row0: src_large
    off = 6*NE + e; if (off < out_size) out[off] = fsp;  // edge_index row0: src_pos
    off = 7*NE + e; if (off < out_size) out[off] = fi;   // edge_index row1: dst_large
    off = 8*NE + e; if (off < out_size) out[off] = fi;   // edge_index row1: dst_pos
}

// ---------------- launcher (passes ONLY harness-provided pointers) ----------------
extern "C" void kernel_launch(void* const* d_in, const int* in_sizes, int n_in,
                              void* d_out, int out_size) {
    const float* x     = (const float*)d_in[0];
    const float* pos   = (const float*)d_in[1];
    const float* noise = (const float*)d_in[2];
    const float* W     = (const float*)d_in[3];
    const float* b     = (const float*)d_in[4];
    const float* gamma = (const float*)d_in[5];
    const float* beta  = (const float*)d_in[6];
    const float* t     = (const float*)d_in[7];
    float* out = (float*)d_out;

    int nb = (N_NODES + 127) / 128;   // 79

    gemm_kernel<<<nb, 128>>>(x, W, b);
    bn_stats<<<D_OUT, 256>>>();
    emb_kernel<<<nb, 128>>>(noise, pos, gamma, beta);

    {
        dim3 g(nb, NCHUNK);
        knn_kernel<D_OUT, 0><<<g, 128>>>(nullptr);
        knn_kernel<3,     1><<<g, 128>>>(pos);
    }
    merge_emb_kernel<<<nb, 128>>>();
    merge_pos_kernel<<<nb, 128>>>();

    out_kernel<<<(NE + 255)/256, 256>>>(t, out, out_size);
}